// round 14
// baseline (speedup 1.0000x reference)
#include <cuda_runtime.h>
#include <cuda_fp16.h>
#include <mma.h>
#include <math.h>
#include <cstdint>

using namespace nvcuda;

// ----------------------------------------------------------------------------
// TinyByteModel forward. Single-term fp16 wmma GEMMs; conv1 via vocab-factored
// P table; flash-lite attention (K/V staged once per (b,h) in smem);
// update fused into down-GEMM epilogue.
// ----------------------------------------------------------------------------

constexpr int cB = 4, cT = 8192, cD = 1024, cP = 512, cS = 4, cL = 4;
constexpr int cNH = 16, cNKV = 4, cHD = 64, cFF = 4096, cKC = 256, cV = 257;
constexpr int cSEG = 16;
constexpr int cQKV = cD + 2 * cNKV * cHD; // 1536
constexpr int cVP = 384;
constexpr int cVPAD = 384;

typedef __half f16;

// ------------------------------- scratch ------------------------------------
__device__ f16   g_embF[cVPAD * cD];
__device__ f16   g_wt1F[cD * 1536];
__device__ float g_P[cVPAD * 1536];
__device__ float g_h1[(size_t)cB * cT * (cD / 2)];
__device__ float g_lg[cB * cT];
__device__ float g_ent[cB * cP];
__device__ float g_xp[cB * cP * cD];
__device__ f16   g_xpF[cB * cP * cD];
__device__ float g_cosc[cP * cHD];
__device__ float g_sinc[cP * cHD];
__device__ float g_rl[cB * cP];
__device__ int   g_sel[cB * cKC];
__device__ float g_gg[cB * cKC];
__device__ float g_xs[cB * cKC * cD];
__device__ f16   g_hF[cB * cKC * cD];
__device__ f16   g_wqkvF[(size_t)cL * cD * cQKV];
__device__ float g_qkv[cB * cKC * cQKV];
__device__ f16   g_attF[cB * cKC * cD];
__device__ f16   g_oWF[(size_t)cL * cD * cD];
__device__ float g_ao[cB * cKC * cD];
__device__ f16   g_h2F[cB * cKC * cD];
__device__ f16   g_guWF[(size_t)cL * cD * 2 * cFF];
__device__ f16   g_actF[cB * cKC * cFF];
__device__ f16   g_dnWF[(size_t)cL * cFF * cD];
__device__ f16   g_pjWF[(size_t)cD * cS * cD];
__device__ float g_proj[(size_t)cB * cP * cS * cD];
__device__ f16   g_m1WF[cD * 256];
__device__ float g_hmid[cB * cP * 256];
__device__ float g_win[cB * cP * cS];
__device__ f16   g_yF[(size_t)cB * cP * cS * cD];
__device__ f16   g_hdWF[cD * cVP];

// ------------------------------- helpers ------------------------------------
__device__ __forceinline__ float geluf(float x) {
    float x3 = x * x * x;
    return 0.5f * x * (1.0f + tanhf(0.7978845608028654f * (x + 0.044715f * x3)));
}
__device__ __forceinline__ float sigmoidf_(float x) { return 1.0f / (1.0f + expf(-x)); }
__device__ __forceinline__ unsigned smem_u32(const void* p) {
    return (unsigned)__cvta_generic_to_shared(p);
}
__device__ __forceinline__ void cp16(unsigned dst, const void* src, int srcBytes) {
    asm volatile("cp.async.cg.shared.global [%0], [%1], 16, %2;\n"
                 :: "r"(dst), "l"(src), "r"(srcBytes));
}
__device__ __forceinline__ void cp_commit() { asm volatile("cp.async.commit_group;\n"); }
template <int N>
__device__ __forceinline__ void cp_wait() {
    asm volatile("cp.async.wait_group %0;\n" :: "n"(N));
}

__device__ __forceinline__ float blockReduceSum256(float v, float* red) {
#pragma unroll
    for (int o = 16; o; o >>= 1) v += __shfl_xor_sync(0xffffffffu, v, o);
    if ((threadIdx.x & 31) == 0) red[threadIdx.x >> 5] = v;
    __syncthreads();
    if (threadIdx.x < 8) {
        float t = red[threadIdx.x];
#pragma unroll
        for (int o = 4; o; o >>= 1) t += __shfl_xor_sync(0xffu, t, o);
        if (threadIdx.x == 0) red[0] = t;
    }
    __syncthreads();
    return red[0];
}

// --------------------------- tensor-core GEMM --------------------------------
// C[M,N] = A[M,K] @ B[K,Nb] (use N cols), single fp16 operands, fp32 accum.
// EPI: 0 none, 1 +bias, 2 gelu(+bias), 3 swiglu->OH, 4 down+update fusion.
constexpr int PA = 40;
constexpr int PB = 136;
constexpr int PC = 132;

constexpr size_t smBytes(int BM, int STAGES) {
    return (size_t)STAGES * (BM * PA + 32 * PB) * sizeof(f16);
}

template <int BM, int EPI, int STAGES>
__global__ __launch_bounds__(BM * 2) void tgemm(
    const f16* __restrict__ A, const f16* __restrict__ Bm,
    float* __restrict__ C, f16* __restrict__ OH,
    int M, int N, int Nb, int K, const float* __restrict__ bias)
{
    constexpr int NTH = BM * 2;
    constexpr int WR = BM / 32;
    constexpr int ITA = (BM * 4) / NTH;
    constexpr int ITB = 512 / NTH;
    extern __shared__ __align__(16) char dsm[];
    f16* Abuf = reinterpret_cast<f16*>(dsm);
    f16* Bbuf = Abuf + STAGES * BM * PA;

    const int tid = threadIdx.x;
    const int warpId = tid >> 5;
    const int wrow = warpId % WR;
    const int wcol = warpId / WR;
    const int bm = blockIdx.y * BM;
    const int bn = blockIdx.x * 128;

    wmma::fragment<wmma::accumulator, 16, 16, 16, float> acc[2][4];
#pragma unroll
    for (int i = 0; i < 2; i++)
#pragma unroll
        for (int j = 0; j < 4; j++) wmma::fill_fragment(acc[i][j], 0.0f);

    auto loadStage = [&](int st, int k0) {
#pragma unroll
        for (int u = 0; u < ITA; u++) {
            int c = tid + u * NTH;
            int row = c >> 2, c8 = (c & 3) * 8;
            size_t off = (size_t)(bm + row) * K + k0 + c8;
            cp16(smem_u32(Abuf + st * BM * PA + row * PA + c8), A + off, 16);
        }
#pragma unroll
        for (int u = 0; u < ITB; u++) {
            int c = tid + u * NTH;
            int row = c >> 4, c8 = (c & 15) * 8;
            size_t off = (size_t)(k0 + row) * Nb + bn + c8;
            cp16(smem_u32(Bbuf + st * 32 * PB + row * PB + c8), Bm + off, 16);
        }
    };

    const int nk = K / 32;
#pragma unroll
    for (int s = 0; s < STAGES - 1; s++) {
        loadStage(s, s * 32);
        cp_commit();
    }

    for (int i = 0; i < nk; i++) {
        cp_wait<STAGES - 2>();
        __syncthreads();
        if (i + STAGES - 1 < nk)
            loadStage((i + STAGES - 1) % STAGES, (i + STAGES - 1) * 32);
        cp_commit();
        int st = i % STAGES;
        const f16* As = Abuf + st * BM * PA;
        const f16* Bs = Bbuf + st * 32 * PB;
#pragma unroll
        for (int kk = 0; kk < 32; kk += 16) {
            wmma::fragment<wmma::matrix_a, 16, 16, 16, f16, wmma::row_major> a[2];
#pragma unroll
            for (int i2 = 0; i2 < 2; i2++)
                wmma::load_matrix_sync(a[i2], As + (wrow * 32 + i2 * 16) * PA + kk, PA);
#pragma unroll
            for (int j = 0; j < 4; j++) {
                wmma::fragment<wmma::matrix_b, 16, 16, 16, f16, wmma::row_major> b;
                wmma::load_matrix_sync(b, Bs + kk * PB + wcol * 64 + j * 16, PB);
#pragma unroll
                for (int i2 = 0; i2 < 2; i2++)
                    wmma::mma_sync(acc[i2][j], a[i2], b, acc[i2][j]);
            }
        }
        __syncthreads();
    }

    if (EPI == 0 && bn + 128 <= N && (N & 3) == 0) {
#pragma unroll
        for (int i = 0; i < 2; i++)
#pragma unroll
            for (int j = 0; j < 4; j++)
                wmma::store_matrix_sync(
                    C + (size_t)(bm + wrow * 32 + i * 16) * N + bn + wcol * 64 + j * 16,
                    acc[i][j], N, wmma::mem_row_major);
        return;
    }

    float* Cs = reinterpret_cast<float*>(dsm);
#pragma unroll 1
    for (int wr = 0; wr < WR; wr++) {
        if (wrow == wr) {
#pragma unroll
            for (int i = 0; i < 2; i++)
#pragma unroll
                for (int j = 0; j < 4; j++)
                    wmma::store_matrix_sync(&Cs[(i * 16) * PC + wcol * 64 + j * 16],
                                            acc[i][j], PC, wmma::mem_row_major);
        }
        __syncthreads();
        if (EPI == 3) {
            for (int idx = tid; idx < 32 * 64; idx += NTH) {
                int r = idx >> 6, c = idx & 63;
                float g = Cs[r * PC + c];
                float u = Cs[r * PC + 64 + c];
                float v = g * sigmoidf_(g) * u;
                OH[(size_t)(bm + wr * 32 + r) * (N >> 1) + (bn >> 1) + c] = __float2half(v);
            }
        } else if (EPI == 4) {
            // down-proj + residual update: out = xs + gg*(ao + ff), scatter to xp
            for (int idx = tid; idx < 32 * 128; idx += NTH) {
                int r = idx >> 7, c = idx & 127;
                int row = bm + wr * 32 + r;
                int gc = bn + c;
                int b = row >> 8;
                int p = g_sel[row];
                float gg = g_gg[row];
                size_t ro = (size_t)row * cD + gc;
                float v = g_xs[ro] + gg * (g_ao[ro] + Cs[r * PC + c]);
                size_t oo = ((size_t)(b * cP + p)) * cD + gc;
                g_xp[oo] = v;
                g_xpF[oo] = __float2half(v);
            }
        } else {
            for (int idx = tid; idx < 32 * 128; idx += NTH) {
                int r = idx >> 7, c = idx & 127;
                int gc = bn + c;
                if (gc < N) {
                    float v = Cs[r * PC + c];
                    if (EPI >= 1) v += bias[gc];
                    if (EPI == 2) v = geluf(v);
                    C[(size_t)(bm + wr * 32 + r) * N + gc] = v;
                }
            }
        }
        __syncthreads();
    }
}

// ------------------------------- small kernels ------------------------------

__global__ void k_cvtEmb(const float* __restrict__ emb) {
    int idx = blockIdx.x * 256 + threadIdx.x;
    if (idx >= cVPAD * cD) return;
    int v = idx >> 10;
    g_embF[idx] = __float2half((v < cV) ? emb[idx] : 0.f);
}

__global__ void k_tw1(const float* __restrict__ w1) {
    int idx = blockIdx.x * 256 + threadIdx.x;
    if (idx >= cD * 1536) return;
    int ci = idx / 1536, n = idx % 1536;
    int kc = n / 512, co = n % 512;
    g_wt1F[idx] = __float2half(w1[(size_t)co * 3072 + ci * 3 + kc]);
}

__global__ void k_conv1sum(const int* __restrict__ tok, const float* __restrict__ b1) {
    int row = blockIdx.x;
    int b = row >> 13, t = row & 8191;
    int tid = threadIdx.x;
    int co = tid * 4;
    int v1 = tok[b * cT + t];
    float4 acc = *reinterpret_cast<const float4*>(b1 + co);
    {
        const float4 p = *reinterpret_cast<const float4*>(g_P + (size_t)v1 * 1536 + 512 + co);
        acc.x += p.x; acc.y += p.y; acc.z += p.z; acc.w += p.w;
    }
    if (t >= 1) {
        int v0 = tok[b * cT + t - 1];
        const float4 p = *reinterpret_cast<const float4*>(g_P + (size_t)v0 * 1536 + co);
        acc.x += p.x; acc.y += p.y; acc.z += p.z; acc.w += p.w;
    }
    if (t + 1 < cT) {
        int v2 = tok[b * cT + t + 1];
        const float4 p = *reinterpret_cast<const float4*>(g_P + (size_t)v2 * 1536 + 1024 + co);
        acc.x += p.x; acc.y += p.y; acc.z += p.z; acc.w += p.w;
    }
    float4 o;
    o.x = geluf(acc.x); o.y = geluf(acc.y); o.z = geluf(acc.z); o.w = geluf(acc.w);
    *reinterpret_cast<float4*>(g_h1 + (size_t)row * 512 + co) = o;
}

__global__ void k_cvtW(const float* __restrict__ src, f16* __restrict__ dst,
                       int rows, int srcCols, int dstCols) {
    int idx = blockIdx.x * 256 + threadIdx.x;
    if (idx >= rows * dstCols) return;
    int r = idx / dstCols, c = idx % dstCols;
    float v = (c < srcCols) ? src[(size_t)r * srcCols + c] : 0.f;
    dst[idx] = __float2half(v);
}

__global__ void k_cvtQKV(const float* __restrict__ qw, const float* __restrict__ kw,
                         const float* __restrict__ vw, f16* __restrict__ dst) {
    int idx = blockIdx.x * 256 + threadIdx.x;
    if (idx >= cD * cQKV) return;
    int d = idx / cQKV, c = idx % cQKV;
    float v;
    if (c < 1024) v = qw[(size_t)d * 1024 + c];
    else if (c < 1280) v = kw[(size_t)d * 256 + (c - 1024)];
    else v = vw[(size_t)d * 256 + (c - 1280)];
    dst[idx] = __float2half(v);
}

__global__ void k_cvtGU(const float* __restrict__ gw, const float* __restrict__ uw,
                        f16* __restrict__ dst) {
    int idx = blockIdx.x * 256 + threadIdx.x;
    int c = idx & (2 * cFF - 1);
    int r = idx >> 13;
    int j = c >> 7, q = c & 127;
    float v = (q < 64) ? gw[(size_t)r * cFF + j * 64 + q]
                       : uw[(size_t)r * cFF + j * 64 + (q - 64)];
    dst[idx] = __float2half(v);
}

__global__ void k_conv2(const float* __restrict__ w2, const float* __restrict__ b2) {
    int gw = (blockIdx.x * blockDim.x + threadIdx.x) >> 5;
    int lane = threadIdx.x & 31;
    if (gw >= cB * cT) return;
    int b = gw >> 13, t = gw & (cT - 1);
    float acc = 0.f;
#pragma unroll
    for (int k = 0; k < 3; k++) {
        int tt = t + k - 1;
        if ((unsigned)tt >= (unsigned)cT) continue;
        const float* hrow = g_h1 + ((size_t)(b * cT + tt)) * 512;
        for (int ci = lane; ci < 512; ci += 32)
            acc += hrow[ci] * w2[ci * 3 + k];
    }
#pragma unroll
    for (int o = 16; o; o >>= 1) acc += __shfl_xor_sync(0xffffffffu, acc, o);
    if (lane == 0) g_lg[gw] = acc + b2[0];
}

__global__ void k_patch(const int* __restrict__ tok, const float* __restrict__ emb,
                        const float* __restrict__ normw) {
    int rowid = blockIdx.x;
    int b = rowid >> 9, p = rowid & 511;
    __shared__ float red[8];
    __shared__ int sidx;
    int tid = threadIdx.x;
    if (tid == 0) {
        float vals[cSEG];
        float mx = -1e30f;
        const float* lp = g_lg + (size_t)b * cT + p * cSEG;
#pragma unroll
        for (int s2 = 0; s2 < cSEG; s2++) { vals[s2] = lp[s2]; mx = fmaxf(mx, vals[s2]); }
        float sum = 0.f;
#pragma unroll
        for (int s2 = 0; s2 < cSEG; s2++) { vals[s2] = expf(vals[s2] - mx); sum += vals[s2]; }
        float invs = 1.f / sum;
        float bp = 0.f, ent = 0.f;
#pragma unroll
        for (int s2 = 0; s2 < cSEG; s2++) {
            float w = vals[s2] * invs;
            bp += w * (float)(p * cSEG + s2);
            ent -= w * logf(fmaxf(w, 1e-8f));
        }
        ent /= 2.7725887222397811f;
        int idx = (int)bp;
        if (idx < 0) idx = 0;
        if (idx > cT - 1) idx = cT - 1;
        sidx = idx;
        g_ent[rowid] = ent;
    }
    __syncthreads();
    int token = tok[b * cT + sidx];
    const float* src = emb + (size_t)token * cD;
    float4 xv = *reinterpret_cast<const float4*>(src + tid * 4);
    float ss = xv.x * xv.x + xv.y * xv.y + xv.z * xv.z + xv.w * xv.w;
    float tot = blockReduceSum256(ss, red);
    float inv = rsqrtf(tot / 1024.f + 1e-6f);
    float4 wv = *reinterpret_cast<const float4*>(normw + tid * 4);
    float4 o;
    o.x = xv.x * inv * wv.x; o.y = xv.y * inv * wv.y;
    o.z = xv.z * inv * wv.z; o.w = xv.w * inv * wv.w;
    size_t oo = (size_t)rowid * cD + tid * 4;
    *reinterpret_cast<float4*>(g_xp + oo) = o;
    g_xpF[oo + 0] = __float2half(o.x);
    g_xpF[oo + 1] = __float2half(o.y);
    g_xpF[oo + 2] = __float2half(o.z);
    g_xpF[oo + 3] = __float2half(o.w);
}

__global__ void k_ropecache() {
    int idx = blockIdx.x * blockDim.x + threadIdx.x;
    if (idx >= cP * 32) return;
    int p = idx >> 5, i = idx & 31;
    float theta = expf(-logf(10000.f) * (float)i / 32.f);
    float ang = (float)p * theta;
    float c = cosf(ang), s = sinf(ang);
    g_cosc[p * 64 + i] = c; g_cosc[p * 64 + i + 32] = c;
    g_sinc[p * 64 + i] = s; g_sinc[p * 64 + i + 32] = s;
}

__global__ void k_router(const float* __restrict__ rw) {
    int gw = (blockIdx.x * blockDim.x + threadIdx.x) >> 5;
    int lane = threadIdx.x & 31;
    if (gw >= cB * cP) return;
    const float* xr = g_xp + (size_t)gw * cD;
    float acc = 0.f;
    for (int d = lane * 4; d < cD; d += 128) {
        float4 xv = *reinterpret_cast<const float4*>(xr + d);
        float4 wv = *reinterpret_cast<const float4*>(rw + d);
        acc += xv.x * wv.x + xv.y * wv.y + xv.z * wv.z + xv.w * wv.w;
    }
#pragma unroll
    for (int o = 16; o; o >>= 1) acc += __shfl_xor_sync(0xffffffffu, acc, o);
    if (lane == 0) g_rl[gw] = acc + g_ent[gw];
}

__global__ void k_topk() {
    int b = blockIdx.x;
    __shared__ float vals[cP];
    __shared__ unsigned msk[16];
    int p = threadIdx.x;
    vals[p] = g_rl[b * cP + p];
    __syncthreads();
    float v = vals[p];
    int rank = 0;
    for (int j = 0; j < cP; j++) {
        float u = vals[j];
        rank += (u > v) || (u == v && j < p);
    }
    bool selq = rank < cKC;
    unsigned bal = __ballot_sync(0xffffffffu, selq);
    if ((p & 31) == 0) msk[p >> 5] = bal;
    __syncthreads();
    if (selq) {
        int pos = 0;
        int w = p >> 5;
        for (int ww = 0; ww < w; ww++) pos += __popc(msk[ww]);
        pos += __popc(bal & ((1u << (p & 31)) - 1u));
        g_sel[b * cKC + pos] = p;
        g_gg[b * cKC + pos] = sigmoidf_(v);
    }
}

__global__ void k_gather_rms(const float* __restrict__ lnw) {
    int row = blockIdx.x;
    int b = row >> 8;
    int p = g_sel[row];
    __shared__ float red[8];
    int tid = threadIdx.x;
    const float* src = g_xp + ((size_t)(b * cP + p)) * cD;
    float4 xv = *reinterpret_cast<const float4*>(src + tid * 4);
    *reinterpret_cast<float4*>(g_xs + (size_t)row * cD + tid * 4) = xv;
    float ss = xv.x * xv.x + xv.y * xv.y + xv.z * xv.z + xv.w * xv.w;
    float tot = blockReduceSum256(ss, red);
    float inv = rsqrtf(tot / 1024.f + 1e-6f);
    float4 wv = *reinterpret_cast<const float4*>(lnw + tid * 4);
    size_t oo = (size_t)row * cD + tid * 4;
    g_hF[oo + 0] = __float2half(xv.x * inv * wv.x);
    g_hF[oo + 1] = __float2half(xv.y * inv * wv.y);
    g_hF[oo + 2] = __float2half(xv.z * inv * wv.z);
    g_hF[oo + 3] = __float2half(xv.w * inv * wv.w);
}

__global__ void k_rope() {
    int idx = blockIdx.x * 256 + threadIdx.x;
    if (idx >= cB * cKC * 20 * 32) return;
    int d = idx & 31;
    int hh = (idx >> 5) % 20;
    int row = idx / (32 * 20);
    int p = g_sel[row];
    int off = (hh < 16) ? hh * 64 : 1024 + (hh - 16) * 64;
    float* base = g_qkv + (size_t)row * cQKV + off;
    float c = g_cosc[p * 64 + d], s = g_sinc[p * 64 + d];
    float x1 = base[d], x2 = base[d + 32];
    base[d] = x1 * c - x2 * s;
    base[d + 32] = x2 * c + x1 * s;
}

// Flash-lite attention: block = (32 queries) x (b,h). K/V staged once in smem.
constexpr size_t SM_ATT = (size_t)(2 * 256 * 64 + 32 * 257) * 4; // 163968 B
__global__ __launch_bounds__(256) void k_attn2() {
    int qb = blockIdx.x;
    int bh = blockIdx.y;
    int b = bh >> 4, h = bh & 15;
    int kh = h >> 2;
    extern __shared__ float sm[];
    float* Ks = sm;                  // [256][64]
    float* Vs = sm + 256 * 64;       // [256][64]
    float* sc = sm + 2 * 256 * 64;   // [32][257]
    int tid = threadIdx.x;
    const float* base = g_qkv + (size_t)b * cKC * cQKV;
    for (int idx = tid; idx < 256 * 64; idx += 256) {
        int j = idx >> 6, d = idx & 63;
        Ks[idx] = base[(size_t)j * cQKV + 1024 + kh * 64 + d];
        Vs[idx] = base[(size_t)j * cQKV + 1280 + kh * 64 + d];
    }
    __syncthreads();
    int ql = tid >> 3;
    int lane8 = tid & 7;
    int q = qb * 32 + ql;
    float qr[8];
    const float* qrow = base + (size_t)q * cQKV + h * 64 + lane8 * 8;
#pragma unroll
    for (int k = 0; k < 8; k++) qr[k] = qrow[k];
    // scores (8-lane cooperative dot, lane0 writes)
    for (int j = 0; j < 256; j++) {
        const float* kr = Ks + j * 64 + lane8 * 8;
        float p = 0.f;
#pragma unroll
        for (int k = 0; k < 8; k++) p += qr[k] * kr[k];
#pragma unroll
        for (int o = 4; o; o >>= 1) p += __shfl_xor_sync(0xffffffffu, p, o);
        if (lane8 == 0) sc[ql * 257 + j] = (j <= q) ? p * 0.125f : -1e30f;
    }
    __syncwarp();
    // softmax (unnormalized exp stored; 1/sum via shfl)
    float m = -1e30f;
    for (int j = lane8; j < 256; j += 8) m = fmaxf(m, sc[ql * 257 + j]);
#pragma unroll
    for (int o = 4; o; o >>= 1) m = fmaxf(m, __shfl_xor_sync(0xffffffffu, m, o));
    float s = 0.f;
    for (int j = lane8; j < 256; j += 8) {
        float e = expf(sc[ql * 257 + j] - m);
        sc[ql * 257 + j] = e;
        s += e;
    }
#pragma unroll
    for (int o = 4; o; o >>= 1) s += __shfl_xor_sync(0xffffffffu, s, o);
    float inv = 1.f / s;
    __syncwarp();
    // output
    float acc[8] = {0, 0, 0, 0, 0, 0, 0, 0};
    for (int j = 0; j < 256; j++) {
        float p = sc[ql * 257 + j];
        const float* vr = Vs + j * 64 + lane8 * 8;
#pragma unroll
        for (int k = 0; k < 8; k++) acc[k] += p * vr[k];
    }
    size_t oo = ((size_t)(b * cKC) + q) * cD + h * 64 + lane8 * 8;
#pragma unroll
    for (int k = 0; k < 8; k++) g_attF[oo + k] = __float2half(acc[k] * inv);
}

__global__ void k_addrms(const float* __restrict__ w) {
    int row = blockIdx.x;
    __shared__ float red[8];
    int tid = threadIdx.x;
    size_t ro = (size_t)row * cD + tid * 4;
    float4 xa = *reinterpret_cast<const float4*>(g_xs + ro);
    float4 xb = *reinterpret_cast<const float4*>(g_ao + ro);
    float4 xv;
    xv.x = xa.x + xb.x; xv.y = xa.y + xb.y; xv.z = xa.z + xb.z; xv.w = xa.w + xb.w;
    float ss = xv.x * xv.x + xv.y * xv.y + xv.z * xv.z + xv.w * xv.w;
    float tot = blockReduceSum256(ss, red);
    float inv = rsqrtf(tot / 1024.f + 1e-6f);
    float4 wv = *reinterpret_cast<const float4*>(w + tid * 4);
    g_h2F[ro + 0] = __float2half(xv.x * inv * wv.x);
    g_h2F[ro + 1] = __float2half(xv.y * inv * wv.y);
    g_h2F[ro + 2] = __float2half(xv.z * inv * wv.z);
    g_h2F[ro + 3] = __float2half(xv.w * inv * wv.w);
}

__global__ void k_win(const float* __restrict__ w2, const float* __restrict__ b2) {
    int gw = (blockIdx.x * blockDim.x + threadIdx.x) >> 5;
    int lane = threadIdx.x & 31;
    if (gw >= cB * cP) return;
    const float* hr = g_hmid + (size_t)gw * 256;
    float a0 = 0, a1 = 0, a2 = 0, a3 = 0;
    for (int c = lane; c < 256; c += 32) {
        float xv = hr[c];
        a0 += xv * w2[c * 4 + 0];
        a1 += xv * w2[c * 4 + 1];
        a2 += xv * w2[c * 4 + 2];
        a3 += xv * w2[c * 4 + 3];
    }
#pragma unroll
    for (int o = 16; o; o >>= 1) {
        a0 += __shfl_xor_sync(0xffffffffu, a0, o);
        a1 += __shfl_xor_sync(0xffffffffu, a1, o);
        a2 += __shfl_xor_sync(0xffffffffu, a2, o);
        a3 += __shfl_xor_sync(0xffffffffu, a3, o);
    }
    if (lane == 0) {
        g_win[gw * 4 + 0] = sigmoidf_(a0 + b2[0]);
        g_win[gw * 4 + 1] = sigmoidf_(a1 + b2[1]);
        g_win[gw * 4 + 2] = sigmoidf_(a2 + b2[2]);
        g_win[gw * 4 + 3] = sigmoidf_(a3 + b2[3]);
    }
}

__global__ void k_decnorm(const float* __restrict__ w) {
    int row = blockIdx.x;
    __shared__ float red[8];
    int tid = threadIdx.x;
    float wn = g_win[row];
    const float* src = g_proj + (size_t)row * cD;
    float4 xv = *reinterpret_cast<const float4*>(src + tid * 4);
    xv.x *= wn; xv.y *= wn; xv.z *= wn; xv.w *= wn;
    float ss = xv.x * xv.x + xv.y * xv.y + xv.z * xv.z + xv.w * xv.w;
    float tot = blockReduceSum256(ss, red);
    float inv = rsqrtf(tot / 1024.f + 1e-6f);
    float4 wv = *reinterpret_cast<const float4*>(w + tid * 4);
    size_t oo = (size_t)row * cD + tid * 4;
    g_yF[oo + 0] = __float2half(xv.x * inv * wv.x);
    g_yF[oo + 1] = __float2half(xv.y * inv * wv.y);
    g_yF[oo + 2] = __float2half(xv.z * inv * wv.z);
    g_yF[oo + 3] = __float2half(xv.w * inv * wv.w);
}

// ------------------------------- host ---------------------------------------
extern "C" void kernel_launch(void* const* d_in, const int* in_sizes, int n_in,
                              void* d_out, int out_size) {
    const int*   tokens     = (const int*)d_in[0];
    const float* emb        = (const float*)d_in[1];
    const float* bp_w1      = (const float*)d_in[2];
    const float* bp_b1      = (const float*)d_in[3];
    const float* bp_w2      = (const float*)d_in[4];
    const float* bp_b2      = (const float*)d_in[5];
    const float* enc_norm_w = (const float*)d_in[6];
    const float* router_w   = (const float*)d_in[7];
    const float* ln1_w      = (const float*)d_in[8];
    const float* ln2_w      = (const float*)d_in[9];
    const float* q_w        = (const float*)d_in[10];
    const float* k_w        = (const float*)d_in[11];
    const float* v_w        = (const float*)d_in[12];
    const float* o_w        = (const float*)d_in[13];
    const float* gate_w     = (const float*)d_in[14];
    const float* up_w       = (const float*)d_in[15];
    const float* down_w     = (const float*)d_in[16];
    const float* dec_proj_w = (const float*)d_in[17];
    const float* dec_proj_b = (const float*)d_in[18];
    const float* dec_mlp_w1 = (const float*)d_in[19];
    const float* dec_mlp_b1 = (const float*)d_in[20];
    const float* dec_mlp_w2 = (const float*)d_in[21];
    const float* dec_mlp_b2 = (const float*)d_in[22];
    const float* dec_norm_w = (const float*)d_in[23];
    const float* head_w     = (const float*)d_in[24];

    constexpr size_t SM64  = smBytes(64, 3);
    constexpr size_t SM128 = smBytes(128, 3);

    static bool attrSet = false;
    if (!attrSet) {
        cudaFuncSetAttribute(tgemm<64, 0, 3>, cudaFuncAttributeMaxDynamicSharedMemorySize, (int)SM64);
        cudaFuncSetAttribute(tgemm<64, 2, 3>, cudaFuncAttributeMaxDynamicSharedMemorySize, (int)SM64);
        cudaFuncSetAttribute(tgemm<64, 3, 3>, cudaFuncAttributeMaxDynamicSharedMemorySize, (int)SM64);
        cudaFuncSetAttribute(tgemm<64, 4, 3>, cudaFuncAttributeMaxDynamicSharedMemorySize, (int)SM64);
        cudaFuncSetAttribute(tgemm<128, 0, 3>, cudaFuncAttributeMaxDynamicSharedMemorySize, (int)SM128);
        cudaFuncSetAttribute(tgemm<128, 1, 3>, cudaFuncAttributeMaxDynamicSharedMemorySize, (int)SM128);
        cudaFuncSetAttribute(k_attn2, cudaFuncAttributeMaxDynamicSharedMemorySize, (int)SM_ATT);
        attrSet = true;
    }

    f16 *pembF, *pwt1F, *phF, *pwqkvF, *pattF, *poWF, *ph2F, *pguWF, *pactF,
        *pdnWF, *ppjWF, *pm1WF, *pyF, *phdWF, *pxpF;
    float *pP, *pqkv, *pao, *pproj, *phmid;
    cudaGetSymbolAddress((void**)&pembF, g_embF);
    cudaGetSymbolAddress((void**)&pwt1F, g_wt1F);
    cudaGetSymbolAddress((void**)&pP, g_P);
    cudaGetSymbolAddress((void**)&phF, g_hF);
    cudaGetSymbolAddress((void**)&pwqkvF, g_wqkvF);
    cudaGetSymbolAddress((void**)&pattF, g_attF);
    cudaGetSymbolAddress((void**)&poWF, g_oWF);
    cudaGetSymbolAddress((void**)&ph2F, g_h2F);
    cudaGetSymbolAddress((void**)&pguWF, g_guWF);
    cudaGetSymbolAddress((void**)&pactF, g_actF);
    cudaGetSymbolAddress((void**)&pdnWF, g_dnWF);
    cudaGetSymbolAddress((void**)&ppjWF, g_pjWF);
    cudaGetSymbolAddress((void**)&pm1WF, g_m1WF);
    cudaGetSymbolAddress((void**)&pyF, g_yF);
    cudaGetSymbolAddress((void**)&phdWF, g_hdWF);
    cudaGetSymbolAddress((void**)&pxpF, g_xpF);
    cudaGetSymbolAddress((void**)&pqkv, g_qkv);
    cudaGetSymbolAddress((void**)&pao, g_ao);
    cudaGetSymbolAddress((void**)&pproj, g_proj);
    cudaGetSymbolAddress((void**)&phmid, g_hmid);

    auto SB = [](int n) { return (n + 255) / 256; };

    // byte patcher via P table
    k_cvtEmb<<<SB(cVPAD * cD), 256>>>(emb);
    k_tw1<<<SB(cD * 1536), 256>>>(bp_w1);
    tgemm<128, 0, 3><<<dim3(12, 3), 256, SM128>>>(
        pembF, pwt1F, pP, nullptr, cVPAD, 1536, 1536, cD, nullptr);
    k_conv1sum<<<cB * cT, 128>>>(tokens, bp_b1);
    k_conv2<<<(cB * cT * 32) / 256, 256>>>(bp_w2, bp_b2);
    k_patch<<<cB * cP, 256>>>(tokens, emb, enc_norm_w);
    k_ropecache<<<SB(cP * 32), 256>>>();

    // weight conversions
    for (int l = 0; l < cL; l++) {
        k_cvtQKV<<<SB(cD * cQKV), 256>>>(q_w + (size_t)l * cD * cD,
                                         k_w + (size_t)l * cD * 256,
                                         v_w + (size_t)l * cD * 256,
                                         pwqkvF + (size_t)l * cD * cQKV);
        k_cvtW<<<SB(cD * cD), 256>>>(o_w + (size_t)l * cD * cD,
                                     poWF + (size_t)l * cD * cD, cD, cD, cD);
        k_cvtGU<<<SB(cD * 2 * cFF), 256>>>(gate_w + (size_t)l * cD * cFF,
                                           up_w + (size_t)l * cD * cFF,
                                           pguWF + (size_t)l * cD * 2 * cFF);
        k_cvtW<<<SB(cFF * cD), 256>>>(down_w + (size_t)l * cFF * cD,
                                      pdnWF + (size_t)l * cFF * cD, cFF, cD, cD);
    }
    k_cvtW<<<SB(cD * cS * cD), 256>>>(dec_proj_w, ppjWF, cD, cS * cD, cS * cD);
    k_cvtW<<<SB(cD * 256), 256>>>(dec_mlp_w1, pm1WF, cD, 256, 256);
    k_cvtW<<<SB(cD * cVP), 256>>>(head_w, phdWF, cD, cV, cVP);

    // layers
    for (int l = 0; l < cL; l++) {
        k_router<<<(cB * cP * 32) / 256, 256>>>(router_w + (size_t)l * cD);
        k_topk<<<cB, cP>>>();
        k_gather_rms<<<cB * cKC, 256>>>(ln1_w + (size_t)l * cD);
        tgemm<64, 0, 3><<<dim3(12, 16), 128, SM64>>>(
            phF, pwqkvF + (size_t)l * cD * cQKV, pqkv, nullptr,
            cB * cKC, cQKV, cQKV, cD, nullptr);
        k_rope<<<SB(cB * cKC * 20 * 32), 256>>>();
        k_attn2<<<dim3(8, cB * cNH), 256, SM_ATT>>>();
        tgemm<64, 0, 3><<<dim3(8, 16), 128, SM64>>>(
            pattF, poWF + (size_t)l * cD * cD, pao, nullptr,
            cB * cKC, cD, cD, cD, nullptr);
        k_addrms<<<cB * cKC, 256>>>(ln2_w + (size_t)l * cD);
        tgemm<64, 3, 3><<<dim3(64, 16), 128, SM64>>>(
            ph2F, pguWF + (size_t)l * cD * 2 * cFF, nullptr, pactF,
            cB * cKC, 2 * cFF, 2 * cFF, cD, nullptr);
        tgemm<64, 4, 3><<<dim3(8, 16), 128, SM64>>>(
            pactF, pdnWF + (size_t)l * cFF * cD, nullptr, nullptr,
            cB * cKC, cD, cD, cFF, nullptr);
    }

    // decoder
    tgemm<128, 1, 3><<<dim3(32, 16), 256, SM128>>>(
        pxpF, ppjWF, pproj, nullptr, cB * cP, cS * cD, cS * cD, cD, dec_proj_b);
    tgemm<64, 2, 3><<<dim3(2, 32), 128, SM64>>>(
        pxpF, pm1WF, phmid, nullptr, cB * cP, 256, 256, cD, dec_mlp_b1);
    k_win<<<(cB * cP * 32) / 256, 256>>>(dec_mlp_w2, dec_mlp_b2);
    k_decnorm<<<cB * cP * cS, 256>>>(dec_norm_w);
    tgemm<128, 0, 3><<<dim3(3, 64), 256, SM128>>>(
        pyF, phdWF, (float*)d_out, nullptr, cB * cP * cS, cV, cVP, cD, nullptr);
}

// round 15
// speedup vs baseline: 1.0070x; 1.0070x over previous
#include <cuda_runtime.h>
#include <cuda_fp16.h>
#include <mma.h>
#include <math.h>
#include <cstdint>

using namespace nvcuda;

// ----------------------------------------------------------------------------
// TinyByteModel forward. Single-term fp16 wmma GEMMs; conv1 via vocab-factored
// P table; flash-lite attention (K/V staged once per (b,h) in smem);
// update fused into down-GEMM epilogue.
// ----------------------------------------------------------------------------

constexpr int cB = 4, cT = 8192, cD = 1024, cP = 512, cS = 4, cL = 4;
constexpr int cNH = 16, cNKV = 4, cHD = 64, cFF = 4096, cKC = 256, cV = 257;
constexpr int cSEG = 16;
constexpr int cQKV = cD + 2 * cNKV * cHD; // 1536
constexpr int cVP = 384;
constexpr int cVPAD = 384;

typedef __half f16;

// ------------------------------- scratch ------------------------------------
__device__ f16   g_embF[cVPAD * cD];
__device__ f16   g_wt1F[cD * 1536];
__device__ float g_P[cVPAD * 1536];
__device__ float g_h1[(size_t)cB * cT * (cD / 2)];
__device__ float g_lg[cB * cT];
__device__ float g_ent[cB * cP];
__device__ float g_xp[cB * cP * cD];
__device__ f16   g_xpF[cB * cP * cD];
__device__ float g_cosc[cP * cHD];
__device__ float g_sinc[cP * cHD];
__device__ float g_rl[cB * cP];
__device__ int   g_sel[cB * cKC];
__device__ float g_gg[cB * cKC];
__device__ float g_xs[cB * cKC * cD];
__device__ f16   g_hF[cB * cKC * cD];
__device__ f16   g_wqkvF[(size_t)cL * cD * cQKV];
__device__ float g_qkv[cB * cKC * cQKV];
__device__ f16   g_attF[cB * cKC * cD];
__device__ f16   g_oWF[(size_t)cL * cD * cD];
__device__ float g_ao[cB * cKC * cD];
__device__ f16   g_h2F[cB * cKC * cD];
__device__ f16   g_guWF[(size_t)cL * cD * 2 * cFF];
__device__ f16   g_actF[cB * cKC * cFF];
__device__ f16   g_dnWF[(size_t)cL * cFF * cD];
__device__ f16   g_pjWF[(size_t)cD * cS * cD];
__device__ float g_proj[(size_t)cB * cP * cS * cD];
__device__ f16   g_m1WF[cD * 256];
__device__ float g_hmid[cB * cP * 256];
__device__ float g_win[cB * cP * cS];
__device__ f16   g_yF[(size_t)cB * cP * cS * cD];
__device__ f16   g_hdWF[cD * cVP];

// ------------------------------- helpers ------------------------------------
__device__ __forceinline__ float geluf(float x) {
    float x3 = x * x * x;
    return 0.5f * x * (1.0f + tanhf(0.7978845608028654f * (x + 0.044715f * x3)));
}
__device__ __forceinline__ float sigmoidf_(float x) { return 1.0f / (1.0f + expf(-x)); }
__device__ __forceinline__ unsigned smem_u32(const void* p) {
    return (unsigned)__cvta_generic_to_shared(p);
}
__device__ __forceinline__ void cp16(unsigned dst, const void* src, int srcBytes) {
    asm volatile("cp.async.cg.shared.global [%0], [%1], 16, %2;\n"
                 :: "r"(dst), "l"(src), "r"(srcBytes));
}
__device__ __forceinline__ void cp_commit() { asm volatile("cp.async.commit_group;\n"); }
template <int N>
__device__ __forceinline__ void cp_wait() {
    asm volatile("cp.async.wait_group %0;\n" :: "n"(N));
}

__device__ __forceinline__ float blockReduceSum256(float v, float* red) {
#pragma unroll
    for (int o = 16; o; o >>= 1) v += __shfl_xor_sync(0xffffffffu, v, o);
    if ((threadIdx.x & 31) == 0) red[threadIdx.x >> 5] = v;
    __syncthreads();
    if (threadIdx.x < 8) {
        float t = red[threadIdx.x];
#pragma unroll
        for (int o = 4; o; o >>= 1) t += __shfl_xor_sync(0xffu, t, o);
        if (threadIdx.x == 0) red[0] = t;
    }
    __syncthreads();
    return red[0];
}

// --------------------------- tensor-core GEMM --------------------------------
// C[M,N] = A[M,K] @ B[K,Nb] (use N cols), single fp16 operands, fp32 accum.
// EPI: 0 none, 1 +bias, 2 gelu(+bias), 3 swiglu->OH, 4 down+update fusion.
constexpr int PA = 40;
constexpr int PB = 136;
constexpr int PC = 132;

constexpr size_t smBytes(int BM, int STAGES) {
    return (size_t)STAGES * (BM * PA + 32 * PB) * sizeof(f16);
}

template <int BM, int EPI, int STAGES>
__global__ __launch_bounds__(BM * 2) void tgemm(
    const f16* __restrict__ A, const f16* __restrict__ Bm,
    float* __restrict__ C, f16* __restrict__ OH,
    int M, int N, int Nb, int K, const float* __restrict__ bias)
{
    constexpr int NTH = BM * 2;
    constexpr int WR = BM / 32;
    constexpr int ITA = (BM * 4) / NTH;
    constexpr int ITB = 512 / NTH;
    extern __shared__ __align__(16) char dsm[];
    f16* Abuf = reinterpret_cast<f16*>(dsm);
    f16* Bbuf = Abuf + STAGES * BM * PA;

    const int tid = threadIdx.x;
    const int warpId = tid >> 5;
    const int wrow = warpId % WR;
    const int wcol = warpId / WR;
    const int bm = blockIdx.y * BM;
    const int bn = blockIdx.x * 128;

    wmma::fragment<wmma::accumulator, 16, 16, 16, float> acc[2][4];
#pragma unroll
    for (int i = 0; i < 2; i++)
#pragma unroll
        for (int j = 0; j < 4; j++) wmma::fill_fragment(acc[i][j], 0.0f);

    auto loadStage = [&](int st, int k0) {
#pragma unroll
        for (int u = 0; u < ITA; u++) {
            int c = tid + u * NTH;
            int row = c >> 2, c8 = (c & 3) * 8;
            size_t off = (size_t)(bm + row) * K + k0 + c8;
            cp16(smem_u32(Abuf + st * BM * PA + row * PA + c8), A + off, 16);
        }
#pragma unroll
        for (int u = 0; u < ITB; u++) {
            int c = tid + u * NTH;
            int row = c >> 4, c8 = (c & 15) * 8;
            size_t off = (size_t)(k0 + row) * Nb + bn + c8;
            cp16(smem_u32(Bbuf + st * 32 * PB + row * PB + c8), Bm + off, 16);
        }
    };

    const int nk = K / 32;
#pragma unroll
    for (int s = 0; s < STAGES - 1; s++) {
        loadStage(s, s * 32);
        cp_commit();
    }

    for (int i = 0; i < nk; i++) {
        cp_wait<STAGES - 2>();
        __syncthreads();
        if (i + STAGES - 1 < nk)
            loadStage((i + STAGES - 1) % STAGES, (i + STAGES - 1) * 32);
        cp_commit();
        int st = i % STAGES;
        const f16* As = Abuf + st * BM * PA;
        const f16* Bs = Bbuf + st * 32 * PB;
#pragma unroll
        for (int kk = 0; kk < 32; kk += 16) {
            wmma::fragment<wmma::matrix_a, 16, 16, 16, f16, wmma::row_major> a[2];
#pragma unroll
            for (int i2 = 0; i2 < 2; i2++)
                wmma::load_matrix_sync(a[i2], As + (wrow * 32 + i2 * 16) * PA + kk, PA);
#pragma unroll
            for (int j = 0; j < 4; j++) {
                wmma::fragment<wmma::matrix_b, 16, 16, 16, f16, wmma::row_major> b;
                wmma::load_matrix_sync(b, Bs + kk * PB + wcol * 64 + j * 16, PB);
#pragma unroll
                for (int i2 = 0; i2 < 2; i2++)
                    wmma::mma_sync(acc[i2][j], a[i2], b, acc[i2][j]);
            }
        }
        __syncthreads();
    }

    if (EPI == 0 && bn + 128 <= N && (N & 3) == 0) {
#pragma unroll
        for (int i = 0; i < 2; i++)
#pragma unroll
            for (int j = 0; j < 4; j++)
                wmma::store_matrix_sync(
                    C + (size_t)(bm + wrow * 32 + i * 16) * N + bn + wcol * 64 + j * 16,
                    acc[i][j], N, wmma::mem_row_major);
        return;
    }

    float* Cs = reinterpret_cast<float*>(dsm);
#pragma unroll 1
    for (int wr = 0; wr < WR; wr++) {
        if (wrow == wr) {
#pragma unroll
            for (int i = 0; i < 2; i++)
#pragma unroll
                for (int j = 0; j < 4; j++)
                    wmma::store_matrix_sync(&Cs[(i * 16) * PC + wcol * 64 + j * 16],
                                            acc[i][j], PC, wmma::mem_row_major);
        }
        __syncthreads();
        if (EPI == 3) {
            for (int idx = tid; idx < 32 * 64; idx += NTH) {
                int r = idx >> 6, c = idx & 63;
                float g = Cs[r * PC + c];
                float u = Cs[r * PC + 64 + c];
                float v = g * sigmoidf_(g) * u;
                OH[(size_t)(bm + wr * 32 + r) * (N >> 1) + (bn >> 1) + c] = __float2half(v);
            }
        } else if (EPI == 4) {
            // down-proj + residual update: out = xs + gg*(ao + ff), scatter to xp
            for (int idx = tid; idx < 32 * 128; idx += NTH) {
                int r = idx >> 7, c = idx & 127;
                int row = bm + wr * 32 + r;
                int gc = bn + c;
                int b = row >> 8;
                int p = g_sel[row];
                float gg = g_gg[row];
                size_t ro = (size_t)row * cD + gc;
                float v = g_xs[ro] + gg * (g_ao[ro] + Cs[r * PC + c]);
                size_t oo = ((size_t)(b * cP + p)) * cD + gc;
                g_xp[oo] = v;
                g_xpF[oo] = __float2half(v);
            }
        } else {
            for (int idx = tid; idx < 32 * 128; idx += NTH) {
                int r = idx >> 7, c = idx & 127;
                int gc = bn + c;
                if (gc < N) {
                    float v = Cs[r * PC + c];
                    if (EPI >= 1) v += bias[gc];
                    if (EPI == 2) v = geluf(v);
                    C[(size_t)(bm + wr * 32 + r) * N + gc] = v;
                }
            }
        }
        __syncthreads();
    }
}

// ------------------------------- small kernels ------------------------------

__global__ void k_cvtEmb(const float* __restrict__ emb) {
    int idx = blockIdx.x * 256 + threadIdx.x;
    if (idx >= cVPAD * cD) return;
    int v = idx >> 10;
    g_embF[idx] = __float2half((v < cV) ? emb[idx] : 0.f);
}

__global__ void k_tw1(const float* __restrict__ w1) {
    int idx = blockIdx.x * 256 + threadIdx.x;
    if (idx >= cD * 1536) return;
    int ci = idx / 1536, n = idx % 1536;
    int kc = n / 512, co = n % 512;
    g_wt1F[idx] = __float2half(w1[(size_t)co * 3072 + ci * 3 + kc]);
}

__global__ void k_conv1sum(const int* __restrict__ tok, const float* __restrict__ b1) {
    int row = blockIdx.x;
    int b = row >> 13, t = row & 8191;
    int tid = threadIdx.x;
    int co = tid * 4;
    int v1 = tok[b * cT + t];
    float4 acc = *reinterpret_cast<const float4*>(b1 + co);
    {
        const float4 p = *reinterpret_cast<const float4*>(g_P + (size_t)v1 * 1536 + 512 + co);
        acc.x += p.x; acc.y += p.y; acc.z += p.z; acc.w += p.w;
    }
    if (t >= 1) {
        int v0 = tok[b * cT + t - 1];
        const float4 p = *reinterpret_cast<const float4*>(g_P + (size_t)v0 * 1536 + co);
        acc.x += p.x; acc.y += p.y; acc.z += p.z; acc.w += p.w;
    }
    if (t + 1 < cT) {
        int v2 = tok[b * cT + t + 1];
        const float4 p = *reinterpret_cast<const float4*>(g_P + (size_t)v2 * 1536 + 1024 + co);
        acc.x += p.x; acc.y += p.y; acc.z += p.z; acc.w += p.w;
    }
    float4 o;
    o.x = geluf(acc.x); o.y = geluf(acc.y); o.z = geluf(acc.z); o.w = geluf(acc.w);
    *reinterpret_cast<float4*>(g_h1 + (size_t)row * 512 + co) = o;
}

__global__ void k_cvtW(const float* __restrict__ src, f16* __restrict__ dst,
                       int rows, int srcCols, int dstCols) {
    int idx = blockIdx.x * 256 + threadIdx.x;
    if (idx >= rows * dstCols) return;
    int r = idx / dstCols, c = idx % dstCols;
    float v = (c < srcCols) ? src[(size_t)r * srcCols + c] : 0.f;
    dst[idx] = __float2half(v);
}

__global__ void k_cvtQKV(const float* __restrict__ qw, const float* __restrict__ kw,
                         const float* __restrict__ vw, f16* __restrict__ dst) {
    int idx = blockIdx.x * 256 + threadIdx.x;
    if (idx >= cD * cQKV) return;
    int d = idx / cQKV, c = idx % cQKV;
    float v;
    if (c < 1024) v = qw[(size_t)d * 1024 + c];
    else if (c < 1280) v = kw[(size_t)d * 256 + (c - 1024)];
    else v = vw[(size_t)d * 256 + (c - 1280)];
    dst[idx] = __float2half(v);
}

__global__ void k_cvtGU(const float* __restrict__ gw, const float* __restrict__ uw,
                        f16* __restrict__ dst) {
    int idx = blockIdx.x * 256 + threadIdx.x;
    int c = idx & (2 * cFF - 1);
    int r = idx >> 13;
    int j = c >> 7, q = c & 127;
    float v = (q < 64) ? gw[(size_t)r * cFF + j * 64 + q]
                       : uw[(size_t)r * cFF + j * 64 + (q - 64)];
    dst[idx] = __float2half(v);
}

__global__ void k_conv2(const float* __restrict__ w2, const float* __restrict__ b2) {
    int gw = (blockIdx.x * blockDim.x + threadIdx.x) >> 5;
    int lane = threadIdx.x & 31;
    if (gw >= cB * cT) return;
    int b = gw >> 13, t = gw & (cT - 1);
    float acc = 0.f;
#pragma unroll
    for (int k = 0; k < 3; k++) {
        int tt = t + k - 1;
        if ((unsigned)tt >= (unsigned)cT) continue;
        const float* hrow = g_h1 + ((size_t)(b * cT + tt)) * 512;
        for (int ci = lane; ci < 512; ci += 32)
            acc += hrow[ci] * w2[ci * 3 + k];
    }
#pragma unroll
    for (int o = 16; o; o >>= 1) acc += __shfl_xor_sync(0xffffffffu, acc, o);
    if (lane == 0) g_lg[gw] = acc + b2[0];
}

__global__ void k_patch(const int* __restrict__ tok, const float* __restrict__ emb,
                        const float* __restrict__ normw) {
    int rowid = blockIdx.x;
    int b = rowid >> 9, p = rowid & 511;
    __shared__ float red[8];
    __shared__ int sidx;
    int tid = threadIdx.x;
    if (tid == 0) {
        float vals[cSEG];
        float mx = -1e30f;
        const float* lp = g_lg + (size_t)b * cT + p * cSEG;
#pragma unroll
        for (int s2 = 0; s2 < cSEG; s2++) { vals[s2] = lp[s2]; mx = fmaxf(mx, vals[s2]); }
        float sum = 0.f;
#pragma unroll
        for (int s2 = 0; s2 < cSEG; s2++) { vals[s2] = expf(vals[s2] - mx); sum += vals[s2]; }
        float invs = 1.f / sum;
        float bp = 0.f, ent = 0.f;
#pragma unroll
        for (int s2 = 0; s2 < cSEG; s2++) {
            float w = vals[s2] * invs;
            bp += w * (float)(p * cSEG + s2);
            ent -= w * logf(fmaxf(w, 1e-8f));
        }
        ent /= 2.7725887222397811f;
        int idx = (int)bp;
        if (idx < 0) idx = 0;
        if (idx > cT - 1) idx = cT - 1;
        sidx = idx;
        g_ent[rowid] = ent;
    }
    __syncthreads();
    int token = tok[b * cT + sidx];
    const float* src = emb + (size_t)token * cD;
    float4 xv = *reinterpret_cast<const float4*>(src + tid * 4);
    float ss = xv.x * xv.x + xv.y * xv.y + xv.z * xv.z + xv.w * xv.w;
    float tot = blockReduceSum256(ss, red);
    float inv = rsqrtf(tot / 1024.f + 1e-6f);
    float4 wv = *reinterpret_cast<const float4*>(normw + tid * 4);
    float4 o;
    o.x = xv.x * inv * wv.x; o.y = xv.y * inv * wv.y;
    o.z = xv.z * inv * wv.z; o.w = xv.w * inv * wv.w;
    size_t oo = (size_t)rowid * cD + tid * 4;
    *reinterpret_cast<float4*>(g_xp + oo) = o;
    g_xpF[oo + 0] = __float2half(o.x);
    g_xpF[oo + 1] = __float2half(o.y);
    g_xpF[oo + 2] = __float2half(o.z);
    g_xpF[oo + 3] = __float2half(o.w);
}

__global__ void k_ropecache() {
    int idx = blockIdx.x * blockDim.x + threadIdx.x;
    if (idx >= cP * 32) return;
    int p = idx >> 5, i = idx & 31;
    float theta = expf(-logf(10000.f) * (float)i / 32.f);
    float ang = (float)p * theta;
    float c = cosf(ang), s = sinf(ang);
    g_cosc[p * 64 + i] = c; g_cosc[p * 64 + i + 32] = c;
    g_sinc[p * 64 + i] = s; g_sinc[p * 64 + i + 32] = s;
}

__global__ void k_router(const float* __restrict__ rw) {
    int gw = (blockIdx.x * blockDim.x + threadIdx.x) >> 5;
    int lane = threadIdx.x & 31;
    if (gw >= cB * cP) return;
    const float* xr = g_xp + (size_t)gw * cD;
    float acc = 0.f;
    for (int d = lane * 4; d < cD; d += 128) {
        float4 xv = *reinterpret_cast<const float4*>(xr + d);
        float4 wv = *reinterpret_cast<const float4*>(rw + d);
        acc += xv.x * wv.x + xv.y * wv.y + xv.z * wv.z + xv.w * wv.w;
    }
#pragma unroll
    for (int o = 16; o; o >>= 1) acc += __shfl_xor_sync(0xffffffffu, acc, o);
    if (lane == 0) g_rl[gw] = acc + g_ent[gw];
}

__global__ void k_topk() {
    int b = blockIdx.x;
    __shared__ float vals[cP];
    __shared__ unsigned msk[16];
    int p = threadIdx.x;
    vals[p] = g_rl[b * cP + p];
    __syncthreads();
    float v = vals[p];
    int rank = 0;
    for (int j = 0; j < cP; j++) {
        float u = vals[j];
        rank += (u > v) || (u == v && j < p);
    }
    bool selq = rank < cKC;
    unsigned bal = __ballot_sync(0xffffffffu, selq);
    if ((p & 31) == 0) msk[p >> 5] = bal;
    __syncthreads();
    if (selq) {
        int pos = 0;
        int w = p >> 5;
        for (int ww = 0; ww < w; ww++) pos += __popc(msk[ww]);
        pos += __popc(bal & ((1u << (p & 31)) - 1u));
        g_sel[b * cKC + pos] = p;
        g_gg[b * cKC + pos] = sigmoidf_(v);
    }
}

__global__ void k_gather_rms(const float* __restrict__ lnw) {
    int row = blockIdx.x;
    int b = row >> 8;
    int p = g_sel[row];
    __shared__ float red[8];
    int tid = threadIdx.x;
    const float* src = g_xp + ((size_t)(b * cP + p)) * cD;
    float4 xv = *reinterpret_cast<const float4*>(src + tid * 4);
    *reinterpret_cast<float4*>(g_xs + (size_t)row * cD + tid * 4) = xv;
    float ss = xv.x * xv.x + xv.y * xv.y + xv.z * xv.z + xv.w * xv.w;
    float tot = blockReduceSum256(ss, red);
    float inv = rsqrtf(tot / 1024.f + 1e-6f);
    float4 wv = *reinterpret_cast<const float4*>(lnw + tid * 4);
    size_t oo = (size_t)row * cD + tid * 4;
    g_hF[oo + 0] = __float2half(xv.x * inv * wv.x);
    g_hF[oo + 1] = __float2half(xv.y * inv * wv.y);
    g_hF[oo + 2] = __float2half(xv.z * inv * wv.z);
    g_hF[oo + 3] = __float2half(xv.w * inv * wv.w);
}

__global__ void k_rope() {
    int idx = blockIdx.x * 256 + threadIdx.x;
    if (idx >= cB * cKC * 20 * 32) return;
    int d = idx & 31;
    int hh = (idx >> 5) % 20;
    int row = idx / (32 * 20);
    int p = g_sel[row];
    int off = (hh < 16) ? hh * 64 : 1024 + (hh - 16) * 64;
    float* base = g_qkv + (size_t)row * cQKV + off;
    float c = g_cosc[p * 64 + d], s = g_sinc[p * 64 + d];
    float x1 = base[d], x2 = base[d + 32];
    base[d] = x1 * c - x2 * s;
    base[d + 32] = x2 * c + x1 * s;
}

// Flash-lite attention: block = (32 queries) x (b,h). K/V staged once in smem.
constexpr size_t SM_ATT = (size_t)(2 * 256 * 64 + 32 * 257) * 4; // 163968 B
__global__ __launch_bounds__(256) void k_attn2() {
    int qb = blockIdx.x;
    int bh = blockIdx.y;
    int b = bh >> 4, h = bh & 15;
    int kh = h >> 2;
    extern __shared__ float sm[];
    float* Ks = sm;                  // [256][64]
    float* Vs = sm + 256 * 64;       // [256][64]
    float* sc = sm + 2 * 256 * 64;   // [32][257]
    int tid = threadIdx.x;
    const float* base = g_qkv + (size_t)b * cKC * cQKV;
    for (int idx = tid; idx < 256 * 64; idx += 256) {
        int j = idx >> 6, d = idx & 63;
        Ks[idx] = base[(size_t)j * cQKV + 1024 + kh * 64 + d];
        Vs[idx] = base[(size_t)j * cQKV + 1280 + kh * 64 + d];
    }
    __syncthreads();
    int ql = tid >> 3;
    int lane8 = tid & 7;
    int q = qb * 32 + ql;
    float qr[8];
    const float* qrow = base + (size_t)q * cQKV + h * 64 + lane8 * 8;
#pragma unroll
    for (int k = 0; k < 8; k++) qr[k] = qrow[k];
    // scores (8-lane cooperative dot, lane0 writes)
    for (int j = 0; j < 256; j++) {
        const float* kr = Ks + j * 64 + lane8 * 8;
        float p = 0.f;
#pragma unroll
        for (int k = 0; k < 8; k++) p += qr[k] * kr[k];
#pragma unroll
        for (int o = 4; o; o >>= 1) p += __shfl_xor_sync(0xffffffffu, p, o);
        if (lane8 == 0) sc[ql * 257 + j] = (j <= q) ? p * 0.125f : -1e30f;
    }
    __syncwarp();
    // softmax (unnormalized exp stored; 1/sum via shfl)
    float m = -1e30f;
    for (int j = lane8; j < 256; j += 8) m = fmaxf(m, sc[ql * 257 + j]);
#pragma unroll
    for (int o = 4; o; o >>= 1) m = fmaxf(m, __shfl_xor_sync(0xffffffffu, m, o));
    float s = 0.f;
    for (int j = lane8; j < 256; j += 8) {
        float e = expf(sc[ql * 257 + j] - m);
        sc[ql * 257 + j] = e;
        s += e;
    }
#pragma unroll
    for (int o = 4; o; o >>= 1) s += __shfl_xor_sync(0xffffffffu, s, o);
    float inv = 1.f / s;
    __syncwarp();
    // output
    float acc[8] = {0, 0, 0, 0, 0, 0, 0, 0};
    for (int j = 0; j < 256; j++) {
        float p = sc[ql * 257 + j];
        const float* vr = Vs + j * 64 + lane8 * 8;
#pragma unroll
        for (int k = 0; k < 8; k++) acc[k] += p * vr[k];
    }
    size_t oo = ((size_t)(b * cKC) + q) * cD + h * 64 + lane8 * 8;
#pragma unroll
    for (int k = 0; k < 8; k++) g_attF[oo + k] = __float2half(acc[k] * inv);
}

__global__ void k_addrms(const float* __restrict__ w) {
    int row = blockIdx.x;
    __shared__ float red[8];
    int tid = threadIdx.x;
    size_t ro = (size_t)row * cD + tid * 4;
    float4 xa = *reinterpret_cast<const float4*>(g_xs + ro);
    float4 xb = *reinterpret_cast<const float4*>(g_ao + ro);
    float4 xv;
    xv.x = xa.x + xb.x; xv.y = xa.y + xb.y; xv.z = xa.z + xb.z; xv.w = xa.w + xb.w;
    float ss = xv.x * xv.x + xv.y * xv.y + xv.z * xv.z + xv.w * xv.w;
    float tot = blockReduceSum256(ss, red);
    float inv = rsqrtf(tot / 1024.f + 1e-6f);
    float4 wv = *reinterpret_cast<const float4*>(w + tid * 4);
    g_h2F[ro + 0] = __float2half(xv.x * inv * wv.x);
    g_h2F[ro + 1] = __float2half(xv.y * inv * wv.y);
    g_h2F[ro + 2] = __float2half(xv.z * inv * wv.z);
    g_h2F[ro + 3] = __float2half(xv.w * inv * wv.w);
}

__global__ void k_win(const float* __restrict__ w2, const float* __restrict__ b2) {
    int gw = (blockIdx.x * blockDim.x + threadIdx.x) >> 5;
    int lane = threadIdx.x & 31;
    if (gw >= cB * cP) return;
    const float* hr = g_hmid + (size_t)gw * 256;
    float a0 = 0, a1 = 0, a2 = 0, a3 = 0;
    for (int c = lane; c < 256; c += 32) {
        float xv = hr[c];
        a0 += xv * w2[c * 4 + 0];
        a1 += xv * w2[c * 4 + 1];
        a2 += xv * w2[c * 4 + 2];
        a3 += xv * w2[c * 4 + 3];
    }
#pragma unroll
    for (int o = 16; o; o >>= 1) {
        a0 += __shfl_xor_sync(0xffffffffu, a0, o);
        a1 += __shfl_xor_sync(0xffffffffu, a1, o);
        a2 += __shfl_xor_sync(0xffffffffu, a2, o);
        a3 += __shfl_xor_sync(0xffffffffu, a3, o);
    }
    if (lane == 0) {
        g_win[gw * 4 + 0] = sigmoidf_(a0 + b2[0]);
        g_win[gw * 4 + 1] = sigmoidf_(a1 + b2[1]);
        g_win[gw * 4 + 2] = sigmoidf_(a2 + b2[2]);
        g_win[gw * 4 + 3] = sigmoidf_(a3 + b2[3]);
    }
}

__global__ void k_decnorm(const float* __restrict__ w) {
    int row = blockIdx.x;
    __shared__ float red[8];
    int tid = threadIdx.x;
    float wn = g_win[row];
    const float* src = g_proj + (size_t)row * cD;
    float4 xv = *reinterpret_cast<const float4*>(src + tid * 4);
    xv.x *= wn; xv.y *= wn; xv.z *= wn; xv.w *= wn;
    float ss = xv.x * xv.x + xv.y * xv.y + xv.z * xv.z + xv.w * xv.w;
    float tot = blockReduceSum256(ss, red);
    float inv = rsqrtf(tot / 1024.f + 1e-6f);
    float4 wv = *reinterpret_cast<const float4*>(w + tid * 4);
    size_t oo = (size_t)row * cD + tid * 4;
    g_yF[oo + 0] = __float2half(xv.x * inv * wv.x);
    g_yF[oo + 1] = __float2half(xv.y * inv * wv.y);
    g_yF[oo + 2] = __float2half(xv.z * inv * wv.z);
    g_yF[oo + 3] = __float2half(xv.w * inv * wv.w);
}

// ------------------------------- host ---------------------------------------
extern "C" void kernel_launch(void* const* d_in, const int* in_sizes, int n_in,
                              void* d_out, int out_size) {
    const int*   tokens     = (const int*)d_in[0];
    const float* emb        = (const float*)d_in[1];
    const float* bp_w1      = (const float*)d_in[2];
    const float* bp_b1      = (const float*)d_in[3];
    const float* bp_w2      = (const float*)d_in[4];
    const float* bp_b2      = (const float*)d_in[5];
    const float* enc_norm_w = (const float*)d_in[6];
    const float* router_w   = (const float*)d_in[7];
    const float* ln1_w      = (const float*)d_in[8];
    const float* ln2_w      = (const float*)d_in[9];
    const float* q_w        = (const float*)d_in[10];
    const float* k_w        = (const float*)d_in[11];
    const float* v_w        = (const float*)d_in[12];
    const float* o_w        = (const float*)d_in[13];
    const float* gate_w     = (const float*)d_in[14];
    const float* up_w       = (const float*)d_in[15];
    const float* down_w     = (const float*)d_in[16];
    const float* dec_proj_w = (const float*)d_in[17];
    const float* dec_proj_b = (const float*)d_in[18];
    const float* dec_mlp_w1 = (const float*)d_in[19];
    const float* dec_mlp_b1 = (const float*)d_in[20];
    const float* dec_mlp_w2 = (const float*)d_in[21];
    const float* dec_mlp_b2 = (const float*)d_in[22];
    const float* dec_norm_w = (const float*)d_in[23];
    const float* head_w     = (const float*)d_in[24];

    constexpr size_t SM64  = smBytes(64, 3);
    constexpr size_t SM128 = smBytes(128, 3);

    static bool attrSet = false;
    if (!attrSet) {
        cudaFuncSetAttribute(tgemm<64, 0, 3>, cudaFuncAttributeMaxDynamicSharedMemorySize, (int)SM64);
        cudaFuncSetAttribute(tgemm<64, 2, 3>, cudaFuncAttributeMaxDynamicSharedMemorySize, (int)SM64);
        cudaFuncSetAttribute(tgemm<64, 3, 3>, cudaFuncAttributeMaxDynamicSharedMemorySize, (int)SM64);
        cudaFuncSetAttribute(tgemm<64, 4, 3>, cudaFuncAttributeMaxDynamicSharedMemorySize, (int)SM64);
        cudaFuncSetAttribute(tgemm<128, 0, 3>, cudaFuncAttributeMaxDynamicSharedMemorySize, (int)SM128);
        cudaFuncSetAttribute(tgemm<128, 1, 3>, cudaFuncAttributeMaxDynamicSharedMemorySize, (int)SM128);
        cudaFuncSetAttribute(k_attn2, cudaFuncAttributeMaxDynamicSharedMemorySize, (int)SM_ATT);
        attrSet = true;
    }

    f16 *pembF, *pwt1F, *phF, *pwqkvF, *pattF, *poWF, *ph2F, *pguWF, *pactF,
        *pdnWF, *ppjWF, *pm1WF, *pyF, *phdWF, *pxpF;
    float *pP, *pqkv, *pao, *pproj, *phmid;
    cudaGetSymbolAddress((void**)&pembF, g_embF);
    cudaGetSymbolAddress((void**)&pwt1F, g_wt1F);
    cudaGetSymbolAddress((void**)&pP, g_P);
    cudaGetSymbolAddress((void**)&phF, g_hF);
    cudaGetSymbolAddress((void**)&pwqkvF, g_wqkvF);
    cudaGetSymbolAddress((void**)&pattF, g_attF);
    cudaGetSymbolAddress((void**)&poWF, g_oWF);
    cudaGetSymbolAddress((void**)&ph2F, g_h2F);
    cudaGetSymbolAddress((void**)&pguWF, g_guWF);
    cudaGetSymbolAddress((void**)&pactF, g_actF);
    cudaGetSymbolAddress((void**)&pdnWF, g_dnWF);
    cudaGetSymbolAddress((void**)&ppjWF, g_pjWF);
    cudaGetSymbolAddress((void**)&pm1WF, g_m1WF);
    cudaGetSymbolAddress((void**)&pyF, g_yF);
    cudaGetSymbolAddress((void**)&phdWF, g_hdWF);
    cudaGetSymbolAddress((void**)&pxpF, g_xpF);
    cudaGetSymbolAddress((void**)&pqkv, g_qkv);
    cudaGetSymbolAddress((void**)&pao, g_ao);
    cudaGetSymbolAddress((void**)&pproj, g_proj);
    cudaGetSymbolAddress((void**)&phmid, g_hmid);

    auto SB = [](int n) { return (n + 255) / 256; };

    // byte patcher via P table
    k_cvtEmb<<<SB(cVPAD * cD), 256>>>(emb);
    k_tw1<<<SB(cD * 1536), 256>>>(bp_w1);
    tgemm<128, 0, 3><<<dim3(12, 3), 256, SM128>>>(
        pembF, pwt1F, pP, nullptr, cVPAD, 1536, 1536, cD, nullptr);
    k_conv1sum<<<cB * cT, 128>>>(tokens, bp_b1);
    k_conv2<<<(cB * cT * 32) / 256, 256>>>(bp_w2, bp_b2);
    k_patch<<<cB * cP, 256>>>(tokens, emb, enc_norm_w);
    k_ropecache<<<SB(cP * 32), 256>>>();

    // weight conversions
    for (int l = 0; l < cL; l++) {
        k_cvtQKV<<<SB(cD * cQKV), 256>>>(q_w + (size_t)l * cD * cD,
                                         k_w + (size_t)l * cD * 256,
                                         v_w + (size_t)l * cD * 256,
                                         pwqkvF + (size_t)l * cD * cQKV);
        k_cvtW<<<SB(cD * cD), 256>>>(o_w + (size_t)l * cD * cD,
                                     poWF + (size_t)l * cD * cD, cD, cD, cD);
        k_cvtGU<<<SB(cD * 2 * cFF), 256>>>(gate_w + (size_t)l * cD * cFF,
                                           up_w + (size_t)l * cD * cFF,
                                           pguWF + (size_t)l * cD * 2 * cFF);
        k_cvtW<<<SB(cFF * cD), 256>>>(down_w + (size_t)l * cFF * cD,
                                      pdnWF + (size_t)l * cFF * cD, cFF, cD, cD);
    }
    k_cvtW<<<SB(cD * cS * cD), 256>>>(dec_proj_w, ppjWF, cD, cS * cD, cS * cD);
    k_cvtW<<<SB(cD * 256), 256>>>(dec_mlp_w1, pm1WF, cD, 256, 256);
    k_cvtW<<<SB(cD * cVP), 256>>>(head_w, phdWF, cD, cV, cVP);

    // layers
    for (int l = 0; l < cL; l++) {
        k_router<<<(cB * cP * 32) / 256, 256>>>(router_w + (size_t)l * cD);
        k_topk<<<cB, cP>>>();
        k_gather_rms<<<cB * cKC, 256>>>(ln1_w + (size_t)l * cD);
        tgemm<64, 0, 3><<<dim3(12, 16), 128, SM64>>>(
            phF, pwqkvF + (size_t)l * cD * cQKV, pqkv, nullptr,
            cB * cKC, cQKV, cQKV, cD, nullptr);
        k_rope<<<SB(cB * cKC * 20 * 32), 256>>>();
        k_attn2<<<dim3(8, cB * cNH), 256, SM_ATT>>>();
        tgemm<64, 0, 3><<<dim3(8, 16), 128, SM64>>>(
            pattF, poWF + (size_t)l * cD * cD, pao, nullptr,
            cB * cKC, cD, cD, cD, nullptr);
        k_addrms<<<cB * cKC, 256>>>(ln2_w + (size_t)l * cD);
        tgemm<64, 3, 3><<<dim3(64, 16), 128, SM64>>>(
            ph2F, pguWF + (size_t)l * cD * 2 * cFF, nullptr, pactF,
            cB * cKC, 2 * cFF, 2 * cFF, cD, nullptr);
        tgemm<64, 4, 3><<<dim3(8, 16), 128, SM64>>>(
            pactF, pdnWF + (size_t)l * cFF * cD, nullptr, nullptr,
            cB * cKC, cD, cD, cFF, nullptr);
    }

    // decoder
    tgemm<128, 1, 3><<<dim3(32, 16), 256, SM128>>>(
        pxpF, ppjWF, pproj, nullptr, cB * cP, cS * cD, cS * cD, cD, dec_proj_b);
    tgemm<64, 2, 3><<<dim3(2, 32), 128, SM64>>>(
        pxpF, pm1WF, phmid, nullptr, cB * cP, 256, 256, cD, dec_mlp_b1);
    k_win<<<(cB * cP * 32) / 256, 256>>>(dec_mlp_w2, dec_mlp_b2);
    k_decnorm<<<cB * cP * cS, 256>>>(dec_norm_w);
    tgemm<128, 0, 3><<<dim3(3, 64), 256, SM128>>>(
        pyF, phdWF, (float*)d_out, nullptr, cB * cP * cS, cV, cVP, cD, nullptr);
}